// round 7
// baseline (speedup 1.0000x reference)
#include <cuda_runtime.h>
#include <cuda_fp16.h>
#include <cstdint>
#include <cstddef>

// ---------------------------------------------------------------------------
// y[8192, 11008] = x[8192,4096] @ (W_int8 * group_scales)^T + bias.
// Harness dtype model (evidence rounds 3-4): fp16 tensors are promoted to
// float32. So: x float32, W int32 (int8 values), scales float32 [11008,32],
// bias float32, OUT float32.
// Toolchain targets sm_103 (no 'a'): tcgen05 unavailable -> mma.sync HMMA.
// Pass 0: convert x f32 -> fp16 scratch (lossless: values are fp16-exact).
// Pass 1: dequant W -> fp16 scratch (identical rounding to reference).
// Pass 2: 128x128x32 fp16 GEMM, mma.sync.m16n8k16, fp32 accum, 4-stage
//         cp.async pipeline, fused bias, float32 stores.
// ---------------------------------------------------------------------------

static constexpr int IN_F   = 4096;
static constexpr int OUT_F  = 11008;
static constexpr int M_TOT  = 8192;
static constexpr int GROUPS = 32;

static constexpr int BM = 128;
static constexpr int BN = 128;
static constexpr int BK = 32;
static constexpr int NSTG = 4;
static constexpr int KITERS = IN_F / BK;        // 128
static constexpr int MTILES = M_TOT / BM;       // 64
static constexpr int NTILES = OUT_F / BN;       // 86

static constexpr int ROW_HALFS = BK + 8;        // 40 halves = 80 B row stride
static constexpr int ROW_BYTES = ROW_HALFS * 2; // 80
static constexpr int TILE_BYTES = BM * ROW_BYTES;         // 10240 per operand/stage
static constexpr int B_SM_OFF = NSTG * TILE_BYTES;        // 40960
static constexpr int SM_TOTAL = 2 * NSTG * TILE_BYTES;    // 81920

__device__ __half g_wdq[(size_t)OUT_F * IN_F];  // fp16 dequant scratch (~86 MB)
__device__ __half g_xh[(size_t)M_TOT * IN_F];   // fp16 x scratch (~64 MB)

// ---------------- Pass 0: x float32 -> fp16 ---------------------------------

__global__ void xh_kernel(const float* __restrict__ x) {
    size_t t = (size_t)blockIdx.x * blockDim.x + threadIdx.x;
    size_t e = t * 8;
    const float4* x4 = reinterpret_cast<const float4*>(x + e);
    float4 v0 = x4[0];
    float4 v1 = x4[1];
    __half h[8];
    h[0] = __float2half_rn(v0.x);
    h[1] = __float2half_rn(v0.y);
    h[2] = __float2half_rn(v0.z);
    h[3] = __float2half_rn(v0.w);
    h[4] = __float2half_rn(v1.x);
    h[5] = __float2half_rn(v1.y);
    h[6] = __float2half_rn(v1.z);
    h[7] = __float2half_rn(v1.w);
    *reinterpret_cast<uint4*>(&g_xh[e]) = *reinterpret_cast<const uint4*>(h);
}

// ---------------- Pass 1: dequantize W --------------------------------------

__global__ void dq_kernel(const int* __restrict__ w, const float* __restrict__ sc) {
    size_t t = (size_t)blockIdx.x * blockDim.x + threadIdx.x;
    size_t e = t * 8;
    const int4* w4 = reinterpret_cast<const int4*>(w + e);
    int4 q0 = w4[0];
    int4 q1 = w4[1];
    int o = (int)(e >> 12);
    int g = ((int)e & 4095) >> 7;
    float s = sc[o * GROUPS + g];
    __half h[8];
    h[0] = __float2half_rn(s * (float)q0.x);
    h[1] = __float2half_rn(s * (float)q0.y);
    h[2] = __float2half_rn(s * (float)q0.z);
    h[3] = __float2half_rn(s * (float)q0.w);
    h[4] = __float2half_rn(s * (float)q1.x);
    h[5] = __float2half_rn(s * (float)q1.y);
    h[6] = __float2half_rn(s * (float)q1.z);
    h[7] = __float2half_rn(s * (float)q1.w);
    *reinterpret_cast<uint4*>(&g_wdq[e]) = *reinterpret_cast<const uint4*>(h);
}

// ---------------- Pass 2: HMMA GEMM ----------------------------------------

#define CP_ASYNC16(sm, gm) \
    asm volatile("cp.async.cg.shared.global [%0], [%1], 16;" :: "r"(sm), "l"(gm))
#define CP_COMMIT() asm volatile("cp.async.commit_group;" ::: "memory")
#define CP_WAIT2()  asm volatile("cp.async.wait_group 2;"  ::: "memory")

__device__ __forceinline__ uint32_t smem_u32(const void* p) {
    uint32_t a;
    asm("{ .reg .u64 t; cvta.to.shared.u64 t, %1; cvt.u32.u64 %0, t; }"
        : "=r"(a) : "l"(p));
    return a;
}

__device__ __forceinline__ void mma16816(float c[4], uint32_t a0, uint32_t a1,
                                         uint32_t a2, uint32_t a3,
                                         uint32_t b0, uint32_t b1) {
    asm volatile(
        "mma.sync.aligned.m16n8k16.row.col.f32.f16.f16.f32 "
        "{%0,%1,%2,%3}, {%4,%5,%6,%7}, {%8,%9}, {%0,%1,%2,%3};"
        : "+f"(c[0]), "+f"(c[1]), "+f"(c[2]), "+f"(c[3])
        : "r"(a0), "r"(a1), "r"(a2), "r"(a3), "r"(b0), "r"(b1));
}

__global__ void __launch_bounds__(256, 2)
gemm_kernel(const float* __restrict__ bias, float* __restrict__ out) {
    extern __shared__ __align__(16) char smem[];
    const uint32_t sb = smem_u32(smem);
    const int tid = threadIdx.x;
    const int wid = tid >> 5;
    const int lane = tid & 31;
    const int g = lane >> 2;     // row group within mma tile
    const int t = lane & 3;      // k-pair / n-pair selector

    const int bid = blockIdx.x;
    const int mi = bid & (MTILES - 1);   // M fastest -> W band stays hot in L2
    const int ni = bid >> 6;
    const int m0 = mi * BM;
    const int n0 = ni * BN;

    const int wr = wid >> 2;     // warp row (0..1) -> 64 M rows
    const int wc = wid & 3;      // warp col (0..3) -> 32 N cols

    // ---- global/smem slots for cp.async: 2 chunks of A + 2 of B per thread
    const char* gA[2];
    const char* gB[2];
    uint32_t    sA[2], sB[2];
    #pragma unroll
    for (int r = 0; r < 2; r++) {
        int chunk = r * 256 + tid;
        int row = chunk >> 2;
        int seg = chunk & 3;
        gA[r] = reinterpret_cast<const char*>(g_xh + (size_t)(m0 + row) * IN_F) + seg * 16;
        gB[r] = reinterpret_cast<const char*>(g_wdq + (size_t)(n0 + row) * IN_F) + seg * 16;
        sA[r] = (uint32_t)(row * ROW_BYTES + seg * 16);
        sB[r] = (uint32_t)(B_SM_OFF + row * ROW_BYTES + seg * 16);
    }

    auto load_stage = [&](int kc) {
        const uint32_t so = (uint32_t)((kc & (NSTG - 1)) * TILE_BYTES);
        const size_t ko = (size_t)kc * (BK * 2);
        #pragma unroll
        for (int r = 0; r < 2; r++) {
            CP_ASYNC16(sb + so + sA[r], gA[r] + ko);
            CP_ASYNC16(sb + so + sB[r], gB[r] + ko);
        }
    };

    // ---- fragment smem byte offsets (within a stage)
    uint32_t aOff[4], bOff[4];
    #pragma unroll
    for (int i = 0; i < 4; i++)
        aOff[i] = (uint32_t)((wr * 64 + i * 16 + g) * ROW_BYTES + 4 * t);
    #pragma unroll
    for (int j = 0; j < 4; j++)
        bOff[j] = (uint32_t)(B_SM_OFF + (wc * 32 + j * 8 + g) * ROW_BYTES + 4 * t);

    float acc[4][4][4];
    #pragma unroll
    for (int i = 0; i < 4; i++)
        #pragma unroll
        for (int j = 0; j < 4; j++)
            #pragma unroll
            for (int q = 0; q < 4; q++) acc[i][j][q] = 0.0f;

    // ---- prologue: fill 3 stages
    load_stage(0); CP_COMMIT();
    load_stage(1); CP_COMMIT();
    load_stage(2); CP_COMMIT();

    #pragma unroll 1
    for (int kc = 0; kc < KITERS; ++kc) {
        const uint32_t stg = (uint32_t)((kc & (NSTG - 1)) * TILE_BYTES);
        CP_WAIT2();
        __syncthreads();

        if (kc + 3 < KITERS) load_stage(kc + 3);
        CP_COMMIT();

        const char* s = smem + stg;
        #pragma unroll
        for (int ks = 0; ks < 2; ks++) {
            const uint32_t ko = (uint32_t)(ks * 32);  // 16 halves
            uint32_t b[4][2];
            #pragma unroll
            for (int j = 0; j < 4; j++) {
                b[j][0] = *reinterpret_cast<const uint32_t*>(s + bOff[j] + ko);
                b[j][1] = *reinterpret_cast<const uint32_t*>(s + bOff[j] + ko + 16);
            }
            #pragma unroll
            for (int i = 0; i < 4; i++) {
                uint32_t a0 = *reinterpret_cast<const uint32_t*>(s + aOff[i] + ko);
                uint32_t a1 = *reinterpret_cast<const uint32_t*>(s + aOff[i] + ko + 8 * ROW_BYTES);
                uint32_t a2 = *reinterpret_cast<const uint32_t*>(s + aOff[i] + ko + 16);
                uint32_t a3 = *reinterpret_cast<const uint32_t*>(s + aOff[i] + ko + 8 * ROW_BYTES + 16);
                #pragma unroll
                for (int j = 0; j < 4; j++)
                    mma16816(acc[i][j], a0, a1, a2, a3, b[j][0], b[j][1]);
            }
        }
    }

    // ---- epilogue: bias + float32 store
    const int m_base = m0 + wr * 64 + g;
    const int n_base = n0 + wc * 32 + 2 * t;
    #pragma unroll
    for (int j = 0; j < 4; j++) {
        const int cc = n_base + j * 8;
        const float b0f = bias[cc];
        const float b1f = bias[cc + 1];
        #pragma unroll
        for (int i = 0; i < 4; i++) {
            const size_t r0 = (size_t)(m_base + i * 16);
            float2 v0 = make_float2(acc[i][j][0] + b0f, acc[i][j][1] + b1f);
            float2 v1 = make_float2(acc[i][j][2] + b0f, acc[i][j][3] + b1f);
            *reinterpret_cast<float2*>(out + r0 * OUT_F + cc) = v0;
            *reinterpret_cast<float2*>(out + (r0 + 8) * OUT_F + cc) = v1;
        }
    }
}

// ---------------- launch ----------------------------------------------------

extern "C" void kernel_launch(void* const* d_in, const int* in_sizes, int n_in,
                              void* d_out, int out_size) {
    const float* x    = reinterpret_cast<const float*>(d_in[0]);
    const int*   w    = reinterpret_cast<const int*>(d_in[1]);
    const float* sc   = reinterpret_cast<const float*>(d_in[2]);
    const float* bias = reinterpret_cast<const float*>(d_in[3]);
    float*       out  = reinterpret_cast<float*>(d_out);

    // Pass 0: x -> fp16 (33,554,432 elems / 2048 per block)
    xh_kernel<<<(unsigned)((size_t)M_TOT * IN_F / 2048), 256>>>(x);
    // Pass 1: dequant W (45,088,768 elems / 2048 per block)
    dq_kernel<<<(unsigned)((size_t)OUT_F * IN_F / 2048), 256>>>(w, sc);

    cudaFuncSetAttribute(gemm_kernel,
                         cudaFuncAttributeMaxDynamicSharedMemorySize, SM_TOTAL);
    gemm_kernel<<<MTILES * NTILES, 256, SM_TOTAL>>>(bias, out);
}